// round 12
// baseline (speedup 1.0000x reference)
#include <cuda_runtime.h>
#include <cuda_bf16.h>
#include <mma.h>
#include <math.h>
#include <stdint.h>

using namespace nvcuda;

// ---------------- problem constants ----------------
#define BATCH 8
#define NA    1614
#define TOPN  6
#define OUTP  224
#define GN    1568              // 8*196 px
#define GK    18432             // 2048*9
#define NSLOT 295               // conv1 slots: k-major, 22 ranges x 13 tiles + 9
#define NS2   144               // conv2 slots (36 ranges x 4 tiles)
#define NS3   72                // conv3 slots (72 ranges x 1 tile)

#define OFF_COORDS 7225344
#define OFF_PROB   7225536
#define OFF_IDX    7225584

// smem: 4 pipeline stages x 12288 bf16 (24KB) = 96KB
#define STG_ELEM 12288
#define DYNSMEM  (4 * STG_ELEM * 2)   // 98304 bytes

// ---------------- scratch globals ----------------
__device__ __nv_bfloat16 g_wAh[128 * GK];
__device__ __nv_bfloat16 g_wAl[128 * GK];
__device__ __nv_bfloat16 g_w2h[128 * 1152];
__device__ __nv_bfloat16 g_w2l[128 * 1152];
__device__ __nv_bfloat16 g_w3h[128 * 1152];
__device__ __nv_bfloat16 g_w3l[128 * 1152];
__device__ __nv_bfloat16 g_rTh[8 * 196 * 2048];
__device__ __nv_bfloat16 g_rTl[8 * 196 * 2048];
__device__ __nv_bfloat16 g_d1h[8 * 196 * 128];
__device__ __nv_bfloat16 g_d1l[8 * 196 * 128];
__device__ __nv_bfloat16 g_d2h[8 * 49 * 128];
__device__ __nv_bfloat16 g_d2l[8 * 49 * 128];
__device__ float g_part[NSLOT][128][128];
__device__ float g_p2w[NS2][128][128];
__device__ float g_p3w[NS3][128][128];
__device__ float g_d1[BATCH][128][196];
__device__ float g_d2[BATCH][128][49];
__device__ float g_d3[BATCH][128][16];
__device__ int   g_boxes[BATCH][TOPN][4];

// ---------------- helpers ----------------
__device__ __forceinline__ uint32_t smem_u32(const void* p) {
    uint32_t a;
    asm("{ .reg .u64 tmp; cvta.to.shared.u64 tmp, %1; cvt.u32.u64 %0, tmp; }" : "=r"(a) : "l"(p));
    return a;
}
__device__ __forceinline__ void cp16(uint32_t dst, const void* src, bool pred) {
    int sz = pred ? 16 : 0;
    asm volatile("cp.async.cg.shared.global [%0], [%1], 16, %2;" :: "r"(dst), "l"(src), "r"(sz));
}
#define CP_COMMIT() asm volatile("cp.async.commit_group;" ::: "memory")
#define CP_WAIT3()  asm volatile("cp.async.wait_group 3;" ::: "memory")

__device__ __forceinline__ void split_bf16(float a, __nv_bfloat16& hi, __nv_bfloat16& lo) {
    hi = __float2bfloat16(a);
    lo = __float2bfloat16(a - __bfloat162float(hi));
}

// ---------------- merged prep ----------------
__global__ __launch_bounds__(256) void prep_all(const float* __restrict__ wd1,
                                                const float* __restrict__ rpn,
                                                const float* __restrict__ wd2,
                                                const float* __restrict__ wd3) {
    const int bx = blockIdx.x;
    if (bx < 1024) {
        __shared__ float w[2304];
        const int oc = bx >> 3;
        const int ic0 = (bx & 7) * 256;
        const float* src = wd1 + (size_t)oc * GK + (size_t)ic0 * 9;
        for (int i = threadIdx.x; i < 2304; i += 256) w[i] = src[i];
        __syncthreads();
        for (int i = threadIdx.x; i < 2304; i += 256) {
            int t9 = i >> 8, ic = i & 255;
            __nv_bfloat16 hi, lo; split_bf16(w[ic * 9 + t9], hi, lo);
            int o = oc * GK + t9 * 2048 + ic0 + ic;
            g_wAh[o] = hi; g_wAl[o] = lo;
        }
    } else if (bx < 1536) {
        __shared__ float sm_[32][197];
        const int r = bx - 1024;
        const int b = r >> 6;
        const int ic0 = (r & 63) * 32;
        const float* src = rpn + ((size_t)b * 2048 + ic0) * 196;
        for (int i = threadIdx.x; i < 32 * 196; i += 256) {
            int ic = i / 196, p = i - ic * 196;
            sm_[ic][p] = src[ic * 196 + p];
        }
        __syncthreads();
        for (int i = threadIdx.x; i < 32 * 196; i += 256) {
            int p = i >> 5, ic = i & 31;
            __nv_bfloat16 hi, lo; split_bf16(sm_[ic][p], hi, lo);
            int o = (b * 196 + p) * 2048 + ic0 + ic;
            g_rTh[o] = hi; g_rTl[o] = lo;
        }
    } else {
        const bool is3 = (bx >= 1664);
        const int oc = bx - (is3 ? 1664 : 1536);
        const float* src = (is3 ? wd3 : wd2) + (size_t)oc * 1152;
        __nv_bfloat16* dh = (is3 ? g_w3h : g_w2h) + oc * 1152;
        __nv_bfloat16* dl = (is3 ? g_w3l : g_w2l) + oc * 1152;
        for (int o = threadIdx.x; o < 1152; o += 256) {
            int t9 = o >> 7, ic = o & 127;
            __nv_bfloat16 hi, lo; split_bf16(src[ic * 9 + t9], hi, lo);
            dh[o] = hi; dl[o] = lo;
        }
    }
}

// conv1 slot mapping, k-major: c = j*13 + T (j<22), c = 286+T (j=22, T<9)
__device__ __forceinline__ void slot_map(int c, int& T, int& a, int& len) {
    int j;
    if (c < 286) { j = c / 13; T = c - 13 * j; }
    else { j = 22; T = c - 286; }
    if (T < 9) { a = (j < 2) ? 51 * j : 50 * j + 2; len = (j < 2) ? 51 : 50; }
    else       { a = (j < 8) ? 53 * j : 52 * j + 8; len = (j < 8) ? 53 : 52; }
}
__device__ __forceinline__ int slot_id(int T, int j) {
    return (j < 22) ? j * 13 + T : 286 + T;
}

// ---------------- conv-as-GEMM: wmma bf16 hi/lo + 4-stage cp.async ----------------
template<int L>
__global__ __launch_bounds__(256) void conv_wmma() {
    extern __shared__ __nv_bfloat16 sm[];
    const uint32_t sb = smem_u32(sm);
    const int t = threadIdx.x;
    const int warp = t >> 5;

    int T, ka, klen;
    if (L == 1) { slot_map(blockIdx.x, T, ka, klen); }
    else if (L == 2) { T = blockIdx.x & 3; ka = (blockIdx.x >> 2) * 2; klen = 2; }
    else { T = 0; ka = blockIdx.x; klen = 1; }

    const int nbase = T * 128;
    const int wm = (warp >> 2) * 64;
    const int wn = (warp & 3) * 32;
    constexpr int KT = (L == 1) ? GK : 1152;
    constexpr int NREAL = (L == 1) ? GN : (L == 2 ? 392 : 128);

    const __nv_bfloat16* Ah = (L == 1) ? g_wAh : (L == 2) ? g_w2h : g_w3h;
    const __nv_bfloat16* Al = (L == 1) ? g_wAl : (L == 2) ? g_w2l : g_w3l;
    const __nv_bfloat16* Bh = (L == 1) ? g_rTh : (L == 2) ? g_d1h : g_d2h;
    const __nv_bfloat16* Bl = (L == 1) ? g_rTl : (L == 2) ? g_d1l : g_d2l;

    wmma::fragment<wmma::accumulator, 16, 16, 16, float> acc[4][2];
#pragma unroll
    for (int m = 0; m < 4; ++m)
#pragma unroll
        for (int n = 0; n < 2; ++n) wmma::fill_fragment(acc[m][n], 0.f);

    int b_b[2], b_oy[2], b_ox[2]; bool b_v[2];
    int l_arr[2], l_row[2], l_half[2];
#pragma unroll
    for (int i = 0; i < 2; ++i) {
        int idx = i * 256 + t;
        l_arr[i] = idx >> 8; l_row[i] = (idx >> 1) & 127; l_half[i] = idx & 1;
        int px = nbase + l_row[i];
        bool v = px < NREAL;
        int pc = v ? px : 0;
        int bb, pp;
        if (L == 1) { bb = pc / 196; pp = pc - bb * 196; b_oy[i] = pp / 14; b_ox[i] = pp % 14; }
        else if (L == 2) { bb = pc / 49; pp = pc - bb * 49; b_oy[i] = pp / 7; b_ox[i] = pp % 7; }
        else { bb = pc >> 4; pp = pc & 15; b_oy[i] = pp >> 2; b_ox[i] = pp & 3; }
        b_b[i] = bb; b_v[i] = v;
    }

    auto issue = [&](int kc, int stage) {
        int t9, icb;
        if (L == 1) { t9 = kc >> 7; icb = (kc & 127) << 4; }
        else { t9 = kc >> 3; icb = (kc & 7) << 4; }
        const int ky = t9 / 3, kx = t9 - 3 * (t9 / 3);
        const uint32_t bbase = sb + stage * (STG_ELEM * 2);
#pragma unroll
        for (int i = 0; i < 2; ++i) {
            const int rowoff = l_row[i] * 48 + l_half[i] * 16;
            const __nv_bfloat16* srcA = (l_arr[i] ? Al : Ah) + l_row[i] * KT + kc * 16 + l_half[i] * 8;
            cp16(bbase + l_arr[i] * 6144 + rowoff, srcA, true);
            int iy, ix, dimY, dimX;
            if (L == 1) { iy = b_oy[i] + ky - 1; ix = b_ox[i] + kx - 1; dimY = 14; dimX = 14; }
            else if (L == 2) { iy = 2 * b_oy[i] - 1 + ky; ix = 2 * b_ox[i] - 1 + kx; dimY = 14; dimX = 14; }
            else { iy = 2 * b_oy[i] - 1 + ky; ix = 2 * b_ox[i] - 1 + kx; dimY = 7; dimX = 7; }
            bool inb = b_v[i] && ((unsigned)iy < (unsigned)dimY) && ((unsigned)ix < (unsigned)dimX);
            int iyc = inb ? iy : 0, ixc = inb ? ix : 0;
            const __nv_bfloat16* srcB;
            if (L == 1)
                srcB = (l_arr[i] ? Bl : Bh) + ((b_b[i] * 196 + iyc * 14 + ixc) << 11) + icb + l_half[i] * 8;
            else if (L == 2)
                srcB = (l_arr[i] ? Bl : Bh) + ((b_b[i] * 196 + iyc * 14 + ixc) << 7) + icb + l_half[i] * 8;
            else
                srcB = (l_arr[i] ? Bl : Bh) + ((b_b[i] * 49 + iyc * 7 + ixc) << 7) + icb + l_half[i] * 8;
            cp16(bbase + 12288 + l_arr[i] * 6144 + rowoff, srcB, inb);
        }
    };

#pragma unroll
    for (int pf = 0; pf < 3; ++pf) {
        if (pf < klen) issue(ka + pf, pf);
        CP_COMMIT();
    }

    for (int ch = 0; ch < klen; ++ch) {
        const int nxt = ch + 3;
        if (nxt < klen) issue(ka + nxt, nxt & 3);
        CP_COMMIT();
        CP_WAIT3();
        __syncthreads();

        const __nv_bfloat16* bp = sm + (ch & 3) * STG_ELEM;
#pragma unroll
        for (int c = 0; c < 3; ++c) {
            const __nv_bfloat16* Ab = bp + (c == 2 ? 3072 : 0);
            const __nv_bfloat16* Bb = bp + 6144 + (c == 1 ? 3072 : 0);
            wmma::fragment<wmma::matrix_b, 16, 16, 16, __nv_bfloat16, wmma::col_major> fb[2];
#pragma unroll
            for (int n = 0; n < 2; ++n)
                wmma::load_matrix_sync(fb[n], Bb + (wn + n * 16) * 24, 24);
#pragma unroll
            for (int m = 0; m < 4; ++m) {
                wmma::fragment<wmma::matrix_a, 16, 16, 16, __nv_bfloat16, wmma::row_major> fa;
                wmma::load_matrix_sync(fa, Ab + (wm + m * 16) * 24, 24);
                wmma::mma_sync(acc[m][0], fa, fb[0], acc[m][0]);
                wmma::mma_sync(acc[m][1], fa, fb[1], acc[m][1]);
            }
        }
        __syncthreads();
    }

    float* base = (L == 1) ? &g_part[blockIdx.x][0][0]
                : (L == 2) ? &g_p2w[blockIdx.x][0][0]
                           : &g_p3w[blockIdx.x][0][0];
#pragma unroll
    for (int m = 0; m < 4; ++m)
#pragma unroll
        for (int n = 0; n < 2; ++n)
            wmma::store_matrix_sync(base + (wm + m * 16) * 128 + wn + n * 16,
                                    acc[m][n], 128, wmma::mem_row_major);
}

// ---------------- reduce kernels ----------------
__global__ void reduce1(const float* __restrict__ bd1) {
    int i = blockIdx.x * 256 + threadIdx.x;
    if (i >= 128 * 392) return;
    int oc = i / 392;
    int n0 = (i - oc * 392) * 4;
    int T = n0 >> 7, nn = n0 & 127;
    int cnt = (T < 9) ? 23 : 22;
    float4 s = make_float4(0.f, 0.f, 0.f, 0.f);
    for (int j = 0; j < cnt; ++j) {
        float4 v = *(const float4*)&g_part[slot_id(T, j)][oc][nn];
        s.x += v.x; s.y += v.y; s.z += v.z; s.w += v.w;
    }
    float bias = bd1[oc];
    float vals[4] = {s.x + bias, s.y + bias, s.z + bias, s.w + bias};
#pragma unroll
    for (int j = 0; j < 4; ++j) {
        int n = n0 + j;
        int b = n / 196, p = n - b * 196;
        float r = fmaxf(vals[j], 0.f);
        g_d1[b][oc][p] = r;
        __nv_bfloat16 hi, lo; split_bf16(r, hi, lo);
        g_d1h[(b * 196 + p) * 128 + oc] = hi;
        g_d1l[(b * 196 + p) * 128 + oc] = lo;
    }
}

__global__ void reduce2(const float* __restrict__ bd2) {
    int i = blockIdx.x * 256 + threadIdx.x;
    if (i >= 128 * 98) return;
    int oc = i / 98;
    int n0 = (i - oc * 98) * 4;
    int tile = n0 >> 7, col = n0 & 127;
    float4 s = make_float4(0.f, 0.f, 0.f, 0.f);
#pragma unroll
    for (int j = 0; j < 36; ++j) {
        float4 v = *(const float4*)&g_p2w[j * 4 + tile][oc][col];
        s.x += v.x; s.y += v.y; s.z += v.z; s.w += v.w;
    }
    float bias = bd2[oc];
    float vals[4] = {s.x + bias, s.y + bias, s.z + bias, s.w + bias};
#pragma unroll
    for (int j = 0; j < 4; ++j) {
        int px = n0 + j;
        int b = px / 49, p = px - b * 49;
        float r = fmaxf(vals[j], 0.f);
        g_d2[b][oc][p] = r;
        __nv_bfloat16 hi, lo; split_bf16(r, hi, lo);
        g_d2h[(b * 49 + p) * 128 + oc] = hi;
        g_d2l[(b * 49 + p) * 128 + oc] = lo;
    }
}

__global__ void reduce3(const float* __restrict__ bd3) {
    int i = blockIdx.x * 256 + threadIdx.x;
    if (i >= 128 * 32) return;
    int oc = i / 32;
    int n0 = (i - oc * 32) * 4;
    float4 s = make_float4(0.f, 0.f, 0.f, 0.f);
#pragma unroll
    for (int j = 0; j < 72; ++j) {
        float4 v = *(const float4*)&g_p3w[j][oc][n0];
        s.x += v.x; s.y += v.y; s.z += v.z; s.w += v.w;
    }
    float bias = bd3[oc];
    float vals[4] = {s.x + bias, s.y + bias, s.z + bias, s.w + bias};
#pragma unroll
    for (int j = 0; j < 4; ++j) {
        int px = n0 + j;
        int b = px >> 4, p = px & 15;
        g_d3[b][oc][p] = fmaxf(vals[j], 0.f);
    }
}

// ---------------- fused heads + NMS + top-6 (one CTA per batch) ----------------
__global__ __launch_bounds__(1024) void nms_topk_kernel(const float* __restrict__ anchors,
                                                        const float* __restrict__ wt1, const float* __restrict__ bt1,
                                                        const float* __restrict__ wt2, const float* __restrict__ bt2,
                                                        const float* __restrict__ wt3, const float* __restrict__ bt3,
                                                        float* __restrict__ out) {
    __shared__ unsigned long long key[2048];
    const int b = blockIdx.x;
    const int tid = threadIdx.x;

    // compute scores directly into sort keys
    for (int a = tid; a < 2048; a += 1024) {
        unsigned long long k = 0ull;
        if (a < NA) {
            float acc;
            if (a < 1176) {
                int c = a / 196, p = a - c * 196;
                acc = bt1[c];
                const float* w = wt1 + c * 128;
                for (int ic = 0; ic < 128; ++ic) acc += g_d1[b][ic][p] * w[ic];
            } else if (a < 1470) {
                int a2 = a - 1176;
                int c = a2 / 49, p = a2 - c * 49;
                acc = bt2[c];
                const float* w = wt2 + c * 128;
                for (int ic = 0; ic < 128; ++ic) acc += g_d2[b][ic][p] * w[ic];
            } else {
                int a3 = a - 1470;
                int c = a3 / 16, p = a3 & 15;
                acc = bt3[c];
                const float* w = wt3 + c * 128;
                for (int ic = 0; ic < 128; ++ic) acc += g_d3[b][ic][p] * w[ic];
            }
            unsigned u = __float_as_uint(acc);
            unsigned us = (u & 0x80000000u) ? ~u : (u | 0x80000000u);
            k = ((unsigned long long)us << 32) | (unsigned)(~(unsigned)a);
        }
        key[a] = k;
    }

    for (int kk = 2; kk <= 2048; kk <<= 1) {
        for (int j = kk >> 1; j > 0; j >>= 1) {
            __syncthreads();
            for (int i = tid; i < 2048; i += 1024) {
                int ixj = i ^ j;
                if (ixj > i) {
                    unsigned long long x = key[i], y = key[ixj];
                    bool desc = ((i & kk) == 0);
                    if (desc ? (x < y) : (x > y)) { key[i] = y; key[ixj] = x; }
                }
            }
        }
    }
    __syncthreads();

    if (tid == 0) {
        float ky0[TOPN], kx0[TOPN], ky1[TOPN], kx1[TOPN], karea[TOPN], kprob[TOPN];
        int kidx[TOPN];
        int nk = 0;
        for (int r = 0; r < NA && nk < TOPN; ++r) {
            unsigned long long k = key[r];
            int idx = (int)(~(unsigned)k);
            if (idx >= NA) break;
            float y0 = anchors[idx * 4 + 0], x0 = anchors[idx * 4 + 1];
            float y1 = anchors[idx * 4 + 2], x1 = anchors[idx * 4 + 3];
            float area = (y1 - y0) * (x1 - x0);
            bool sup = false;
            for (int s = 0; s < nk; ++s) {
                float ih = fminf(y1, ky1[s]) - fmaxf(y0, ky0[s]); if (ih < 0.f) ih = 0.f;
                float iw = fminf(x1, kx1[s]) - fmaxf(x0, kx0[s]); if (iw < 0.f) iw = 0.f;
                float inter = ih * iw;
                if (inter > 0.25f * (area + karea[s] - inter)) { sup = true; break; }
            }
            if (!sup) {
                unsigned us = (unsigned)(k >> 32);
                unsigned u = (us & 0x80000000u) ? (us ^ 0x80000000u) : ~us;
                ky0[nk] = y0; kx0[nk] = x0; ky1[nk] = y1; kx1[nk] = x1;
                karea[nk] = area; kidx[nk] = idx; kprob[nk] = __uint_as_float(u);
                ++nk;
            }
        }
        int fi = 0;
        while (nk < TOPN) {
            bool used = false;
            for (int s = 0; s < nk; ++s) if (kidx[s] == fi) used = true;
            if (!used) {
                ky0[nk] = anchors[fi * 4 + 0]; kx0[nk] = anchors[fi * 4 + 1];
                ky1[nk] = anchors[fi * 4 + 2]; kx1[nk] = anchors[fi * 4 + 3];
                karea[nk] = 0.f; kidx[nk] = fi; kprob[nk] = -INFINITY;
                ++nk;
            }
            ++fi;
        }
        for (int s = 0; s < TOPN; ++s) {
            int o = b * TOPN + s;
            g_boxes[b][s][0] = (int)kx0[s];
            g_boxes[b][s][1] = (int)ky0[s];
            g_boxes[b][s][2] = (int)kx1[s];
            g_boxes[b][s][3] = (int)ky1[s];
            out[OFF_COORDS + o * 4 + 0] = kx0[s];
            out[OFF_COORDS + o * 4 + 1] = ky0[s];
            out[OFF_COORDS + o * 4 + 2] = kx1[s];
            out[OFF_COORDS + o * 4 + 3] = ky1[s];
            out[OFF_PROB + o] = kprob[s];
            out[OFF_IDX + o] = (float)kidx[s];
        }
    }
}

// ---------------- crop-resize ----------------
__global__ __launch_bounds__(224) void crop_kernel(const float* __restrict__ xin,
                                                   float* __restrict__ out) {
    const int t  = threadIdx.x;
    const int xq = (t % 56) * 4;
    const int oy = blockIdx.x * 4 + t / 56;
    const int c  = blockIdx.y;
    const int bs = blockIdx.z;
    const int b  = bs / TOPN;
    const int s  = bs - b * TOPN;

    const int X0 = g_boxes[b][s][0], Y0 = g_boxes[b][s][1];
    const int X1 = g_boxes[b][s][2], Y1 = g_boxes[b][s][3];

    float ty = __fdiv_rn((float)oy, 223.0f);
    float sy = __fadd_rn((float)Y0, __fmul_rn(ty, (float)(Y1 - 1 - Y0)));
    int y0i = (int)floorf(sy);
    int y1i = min(y0i + 1, Y1 - 1);
    float wy = __fadd_rn(sy, -(float)y0i);

    const float* img = xin + ((size_t)b * 3 + c) * 448 * 448;
    auto fetch = [&](int y, int x) -> float {
        y -= 224; x -= 224;
        if ((unsigned)y < 448u && (unsigned)x < 448u) return img[y * 448 + x];
        return 0.f;
    };

    float4 res;
    float* rp = &res.x;
#pragma unroll
    for (int j = 0; j < 4; ++j) {
        int ox = xq + j;
        float tx = __fdiv_rn((float)ox, 223.0f);
        float sx = __fadd_rn((float)X0, __fmul_rn(tx, (float)(X1 - 1 - X0)));
        int x0i = (int)floorf(sx);
        int x1i = min(x0i + 1, X1 - 1);
        float wx = __fadd_rn(sx, -(float)x0i);

        float f00 = fetch(y0i, x0i), f01 = fetch(y0i, x1i);
        float f10 = fetch(y1i, x0i), f11 = fetch(y1i, x1i);
        float top = (1.f - wx) * f00 + wx * f01;
        float bot = (1.f - wx) * f10 + wx * f11;
        rp[j] = (1.f - wy) * top + wy * bot;
    }
    *(float4*)&out[(((size_t)bs * 3 + c) * OUTP + oy) * OUTP + xq] = res;
}

// ---------------- launch ----------------
extern "C" void kernel_launch(void* const* d_in, const int* in_sizes, int n_in,
                              void* d_out, int out_size) {
    const float* x       = (const float*)d_in[0];
    const float* rpn     = (const float*)d_in[1];
    const float* anchors = (const float*)d_in[2];
    const float* wd1 = (const float*)d_in[3];
    const float* bd1 = (const float*)d_in[4];
    const float* wd2 = (const float*)d_in[5];
    const float* bd2 = (const float*)d_in[6];
    const float* wd3 = (const float*)d_in[7];
    const float* bd3 = (const float*)d_in[8];
    const float* wt1 = (const float*)d_in[9];
    const float* bt1 = (const float*)d_in[10];
    const float* wt2 = (const float*)d_in[11];
    const float* bt2 = (const float*)d_in[12];
    const float* wt3 = (const float*)d_in[13];
    const float* bt3 = (const float*)d_in[14];
    float* out = (float*)d_out;

    cudaFuncSetAttribute(conv_wmma<1>, cudaFuncAttributeMaxDynamicSharedMemorySize, DYNSMEM);
    cudaFuncSetAttribute(conv_wmma<2>, cudaFuncAttributeMaxDynamicSharedMemorySize, DYNSMEM);
    cudaFuncSetAttribute(conv_wmma<3>, cudaFuncAttributeMaxDynamicSharedMemorySize, DYNSMEM);

    prep_all<<<1792, 256>>>(wd1, rpn, wd2, wd3);
    conv_wmma<1><<<NSLOT, 256, DYNSMEM>>>();
    reduce1<<<(128 * 392 + 255) / 256, 256>>>(bd1);
    conv_wmma<2><<<NS2, 256, DYNSMEM>>>();
    reduce2<<<(128 * 98 + 255) / 256, 256>>>(bd2);
    conv_wmma<3><<<NS3, 256, DYNSMEM>>>();
    reduce3<<<(128 * 32 + 255) / 256, 256>>>(bd3);
    nms_topk_kernel<<<BATCH, 1024>>>(anchors, wt1, bt1, wt2, bt2, wt3, bt3, out);
    crop_kernel<<<dim3(56, 3, BATCH * TOPN), 224>>>(x, out);
}

// round 13
// speedup vs baseline: 1.1195x; 1.1195x over previous
#include <cuda_runtime.h>
#include <cuda_bf16.h>
#include <mma.h>
#include <math.h>
#include <stdint.h>

using namespace nvcuda;

// ---------------- problem constants ----------------
#define BATCH 8
#define NA    1614
#define TOPN  6
#define OUTP  224
#define GN    1568              // 8*196 px
#define GK    18432             // 2048*9
#define NSLOT 295               // conv1 slots: k-major, 22 ranges x 13 tiles + 9
#define NS2   72                // conv2 slots (18 ranges x 4 tiles)
#define NS3   36                // conv3 slots (36 ranges x 1 tile)

#define OFF_COORDS 7225344
#define OFF_PROB   7225536
#define OFF_IDX    7225584

// smem: 4 pipeline stages x 12288 bf16 (24KB) = 96KB
#define STG_ELEM 12288
#define DYNSMEM  (4 * STG_ELEM * 2)   // 98304 bytes

// ---------------- scratch globals ----------------
__device__ __nv_bfloat16 g_wAh[128 * GK];
__device__ __nv_bfloat16 g_wAl[128 * GK];
__device__ __nv_bfloat16 g_w2h[128 * 1152];
__device__ __nv_bfloat16 g_w2l[128 * 1152];
__device__ __nv_bfloat16 g_w3h[128 * 1152];
__device__ __nv_bfloat16 g_w3l[128 * 1152];
__device__ __nv_bfloat16 g_rTh[8 * 196 * 2048];
__device__ __nv_bfloat16 g_rTl[8 * 196 * 2048];
__device__ __nv_bfloat16 g_d1h[8 * 196 * 128];
__device__ __nv_bfloat16 g_d1l[8 * 196 * 128];
__device__ __nv_bfloat16 g_d2h[8 * 49 * 128];
__device__ __nv_bfloat16 g_d2l[8 * 49 * 128];
__device__ float g_part[NSLOT][128][128];
__device__ float g_p2w[NS2][128][128];
__device__ float g_p3w[NS3][128][128];
__device__ float g_d1[BATCH][128][196];
__device__ float g_d2[BATCH][128][49];
__device__ float g_d3[BATCH][128][16];
__device__ float g_scores[BATCH][NA];
__device__ int   g_boxes[BATCH][TOPN][4];

// ---------------- helpers ----------------
__device__ __forceinline__ uint32_t smem_u32(const void* p) {
    uint32_t a;
    asm("{ .reg .u64 tmp; cvta.to.shared.u64 tmp, %1; cvt.u32.u64 %0, tmp; }" : "=r"(a) : "l"(p));
    return a;
}
__device__ __forceinline__ void cp16(uint32_t dst, const void* src, bool pred) {
    int sz = pred ? 16 : 0;
    asm volatile("cp.async.cg.shared.global [%0], [%1], 16, %2;" :: "r"(dst), "l"(src), "r"(sz));
}
#define CP_COMMIT() asm volatile("cp.async.commit_group;" ::: "memory")
#define CP_WAIT3()  asm volatile("cp.async.wait_group 3;" ::: "memory")

__device__ __forceinline__ void split_bf16(float a, __nv_bfloat16& hi, __nv_bfloat16& lo) {
    hi = __float2bfloat16(a);
    lo = __float2bfloat16(a - __bfloat162float(hi));
}

// ---------------- merged prep ----------------
__global__ __launch_bounds__(256) void prep_all(const float* __restrict__ wd1,
                                                const float* __restrict__ rpn,
                                                const float* __restrict__ wd2,
                                                const float* __restrict__ wd3) {
    const int bx = blockIdx.x;
    if (bx < 1024) {
        __shared__ float w[2304];
        const int oc = bx >> 3;
        const int ic0 = (bx & 7) * 256;
        const float* src = wd1 + (size_t)oc * GK + (size_t)ic0 * 9;
        for (int i = threadIdx.x; i < 2304; i += 256) w[i] = src[i];
        __syncthreads();
        for (int i = threadIdx.x; i < 2304; i += 256) {
            int t9 = i >> 8, ic = i & 255;
            __nv_bfloat16 hi, lo; split_bf16(w[ic * 9 + t9], hi, lo);
            int o = oc * GK + t9 * 2048 + ic0 + ic;
            g_wAh[o] = hi; g_wAl[o] = lo;
        }
    } else if (bx < 1536) {
        __shared__ float sm_[32][197];
        const int r = bx - 1024;
        const int b = r >> 6;
        const int ic0 = (r & 63) * 32;
        const float* src = rpn + ((size_t)b * 2048 + ic0) * 196;
        for (int i = threadIdx.x; i < 32 * 196; i += 256) {
            int ic = i / 196, p = i - ic * 196;
            sm_[ic][p] = src[ic * 196 + p];
        }
        __syncthreads();
        for (int i = threadIdx.x; i < 32 * 196; i += 256) {
            int p = i >> 5, ic = i & 31;
            __nv_bfloat16 hi, lo; split_bf16(sm_[ic][p], hi, lo);
            int o = (b * 196 + p) * 2048 + ic0 + ic;
            g_rTh[o] = hi; g_rTl[o] = lo;
        }
    } else {
        const bool is3 = (bx >= 1664);
        const int oc = bx - (is3 ? 1664 : 1536);
        const float* src = (is3 ? wd3 : wd2) + (size_t)oc * 1152;
        __nv_bfloat16* dh = (is3 ? g_w3h : g_w2h) + oc * 1152;
        __nv_bfloat16* dl = (is3 ? g_w3l : g_w2l) + oc * 1152;
        for (int o = threadIdx.x; o < 1152; o += 256) {
            int t9 = o >> 7, ic = o & 127;
            __nv_bfloat16 hi, lo; split_bf16(src[ic * 9 + t9], hi, lo);
            dh[o] = hi; dl[o] = lo;
        }
    }
}

// conv1 slot mapping, k-major: c = j*13 + T (j<22), c = 286+T (j=22, T<9)
__device__ __forceinline__ void slot_map(int c, int& T, int& a, int& len) {
    int j;
    if (c < 286) { j = c / 13; T = c - 13 * j; }
    else { j = 22; T = c - 286; }
    if (T < 9) { a = (j < 2) ? 51 * j : 50 * j + 2; len = (j < 2) ? 51 : 50; }
    else       { a = (j < 8) ? 53 * j : 52 * j + 8; len = (j < 8) ? 53 : 52; }
}
__device__ __forceinline__ int slot_id(int T, int j) {
    return (j < 22) ? j * 13 + T : 286 + T;
}

// ---------------- conv-as-GEMM: wmma bf16 hi/lo + 4-stage cp.async ----------------
template<int L>
__global__ __launch_bounds__(256) void conv_wmma() {
    extern __shared__ __nv_bfloat16 sm[];
    const uint32_t sb = smem_u32(sm);
    const int t = threadIdx.x;
    const int warp = t >> 5;

    int T, ka, klen;
    if (L == 1) { slot_map(blockIdx.x, T, ka, klen); }
    else if (L == 2) { T = blockIdx.x & 3; ka = (blockIdx.x >> 2) * 4; klen = 4; }
    else { T = 0; ka = blockIdx.x * 2; klen = 2; }

    const int nbase = T * 128;
    const int wm = (warp >> 2) * 64;
    const int wn = (warp & 3) * 32;
    constexpr int KT = (L == 1) ? GK : 1152;
    constexpr int NREAL = (L == 1) ? GN : (L == 2 ? 392 : 128);

    const __nv_bfloat16* Ah = (L == 1) ? g_wAh : (L == 2) ? g_w2h : g_w3h;
    const __nv_bfloat16* Al = (L == 1) ? g_wAl : (L == 2) ? g_w2l : g_w3l;
    const __nv_bfloat16* Bh = (L == 1) ? g_rTh : (L == 2) ? g_d1h : g_d2h;
    const __nv_bfloat16* Bl = (L == 1) ? g_rTl : (L == 2) ? g_d1l : g_d2l;

    wmma::fragment<wmma::accumulator, 16, 16, 16, float> acc[4][2];
#pragma unroll
    for (int m = 0; m < 4; ++m)
#pragma unroll
        for (int n = 0; n < 2; ++n) wmma::fill_fragment(acc[m][n], 0.f);

    int b_b[2], b_oy[2], b_ox[2]; bool b_v[2];
    int l_arr[2], l_row[2], l_half[2];
#pragma unroll
    for (int i = 0; i < 2; ++i) {
        int idx = i * 256 + t;
        l_arr[i] = idx >> 8; l_row[i] = (idx >> 1) & 127; l_half[i] = idx & 1;
        int px = nbase + l_row[i];
        bool v = px < NREAL;
        int pc = v ? px : 0;
        int bb, pp;
        if (L == 1) { bb = pc / 196; pp = pc - bb * 196; b_oy[i] = pp / 14; b_ox[i] = pp % 14; }
        else if (L == 2) { bb = pc / 49; pp = pc - bb * 49; b_oy[i] = pp / 7; b_ox[i] = pp % 7; }
        else { bb = pc >> 4; pp = pc & 15; b_oy[i] = pp >> 2; b_ox[i] = pp & 3; }
        b_b[i] = bb; b_v[i] = v;
    }

    auto issue = [&](int kc, int stage) {
        int t9, icb;
        if (L == 1) { t9 = kc >> 7; icb = (kc & 127) << 4; }
        else { t9 = kc >> 3; icb = (kc & 7) << 4; }
        const int ky = t9 / 3, kx = t9 - 3 * (t9 / 3);
        const uint32_t bbase = sb + stage * (STG_ELEM * 2);
#pragma unroll
        for (int i = 0; i < 2; ++i) {
            const int rowoff = l_row[i] * 48 + l_half[i] * 16;
            const __nv_bfloat16* srcA = (l_arr[i] ? Al : Ah) + l_row[i] * KT + kc * 16 + l_half[i] * 8;
            cp16(bbase + l_arr[i] * 6144 + rowoff, srcA, true);
            int iy, ix, dimY, dimX;
            if (L == 1) { iy = b_oy[i] + ky - 1; ix = b_ox[i] + kx - 1; dimY = 14; dimX = 14; }
            else if (L == 2) { iy = 2 * b_oy[i] - 1 + ky; ix = 2 * b_ox[i] - 1 + kx; dimY = 14; dimX = 14; }
            else { iy = 2 * b_oy[i] - 1 + ky; ix = 2 * b_ox[i] - 1 + kx; dimY = 7; dimX = 7; }
            bool inb = b_v[i] && ((unsigned)iy < (unsigned)dimY) && ((unsigned)ix < (unsigned)dimX);
            int iyc = inb ? iy : 0, ixc = inb ? ix : 0;
            const __nv_bfloat16* srcB;
            if (L == 1)
                srcB = (l_arr[i] ? Bl : Bh) + ((b_b[i] * 196 + iyc * 14 + ixc) << 11) + icb + l_half[i] * 8;
            else if (L == 2)
                srcB = (l_arr[i] ? Bl : Bh) + ((b_b[i] * 196 + iyc * 14 + ixc) << 7) + icb + l_half[i] * 8;
            else
                srcB = (l_arr[i] ? Bl : Bh) + ((b_b[i] * 49 + iyc * 7 + ixc) << 7) + icb + l_half[i] * 8;
            cp16(bbase + 12288 + l_arr[i] * 6144 + rowoff, srcB, inb);
        }
    };

#pragma unroll
    for (int pf = 0; pf < 3; ++pf) {
        if (pf < klen) issue(ka + pf, pf);
        CP_COMMIT();
    }

    for (int ch = 0; ch < klen; ++ch) {
        const int nxt = ch + 3;
        if (nxt < klen) issue(ka + nxt, nxt & 3);
        CP_COMMIT();
        CP_WAIT3();
        __syncthreads();

        const __nv_bfloat16* bp = sm + (ch & 3) * STG_ELEM;
#pragma unroll
        for (int c = 0; c < 3; ++c) {
            const __nv_bfloat16* Ab = bp + (c == 2 ? 3072 : 0);
            const __nv_bfloat16* Bb = bp + 6144 + (c == 1 ? 3072 : 0);
            wmma::fragment<wmma::matrix_b, 16, 16, 16, __nv_bfloat16, wmma::col_major> fb[2];
#pragma unroll
            for (int n = 0; n < 2; ++n)
                wmma::load_matrix_sync(fb[n], Bb + (wn + n * 16) * 24, 24);
#pragma unroll
            for (int m = 0; m < 4; ++m) {
                wmma::fragment<wmma::matrix_a, 16, 16, 16, __nv_bfloat16, wmma::row_major> fa;
                wmma::load_matrix_sync(fa, Ab + (wm + m * 16) * 24, 24);
                wmma::mma_sync(acc[m][0], fa, fb[0], acc[m][0]);
                wmma::mma_sync(acc[m][1], fa, fb[1], acc[m][1]);
            }
        }
        __syncthreads();
    }

    float* base = (L == 1) ? &g_part[blockIdx.x][0][0]
                : (L == 2) ? &g_p2w[blockIdx.x][0][0]
                           : &g_p3w[blockIdx.x][0][0];
#pragma unroll
    for (int m = 0; m < 4; ++m)
#pragma unroll
        for (int n = 0; n < 2; ++n)
            wmma::store_matrix_sync(base + (wm + m * 16) * 128 + wn + n * 16,
                                    acc[m][n], 128, wmma::mem_row_major);
}

// ---------------- reduce kernels ----------------
__global__ void reduce1(const float* __restrict__ bd1) {
    int i = blockIdx.x * 256 + threadIdx.x;
    if (i >= 128 * 392) return;
    int oc = i / 392;
    int n0 = (i - oc * 392) * 4;
    int T = n0 >> 7, nn = n0 & 127;
    int cnt = (T < 9) ? 23 : 22;
    float4 s = make_float4(0.f, 0.f, 0.f, 0.f);
    for (int j = 0; j < cnt; ++j) {
        float4 v = *(const float4*)&g_part[slot_id(T, j)][oc][nn];
        s.x += v.x; s.y += v.y; s.z += v.z; s.w += v.w;
    }
    float bias = bd1[oc];
    float vals[4] = {s.x + bias, s.y + bias, s.z + bias, s.w + bias};
#pragma unroll
    for (int j = 0; j < 4; ++j) {
        int n = n0 + j;
        int b = n / 196, p = n - b * 196;
        float r = fmaxf(vals[j], 0.f);
        g_d1[b][oc][p] = r;
        __nv_bfloat16 hi, lo; split_bf16(r, hi, lo);
        g_d1h[(b * 196 + p) * 128 + oc] = hi;
        g_d1l[(b * 196 + p) * 128 + oc] = lo;
    }
}

__global__ void reduce2(const float* __restrict__ bd2) {
    int i = blockIdx.x * 256 + threadIdx.x;
    if (i >= 128 * 98) return;
    int oc = i / 98;
    int n0 = (i - oc * 98) * 4;
    int tile = n0 >> 7, col = n0 & 127;
    float4 s = make_float4(0.f, 0.f, 0.f, 0.f);
#pragma unroll
    for (int j = 0; j < 18; ++j) {
        float4 v = *(const float4*)&g_p2w[j * 4 + tile][oc][col];
        s.x += v.x; s.y += v.y; s.z += v.z; s.w += v.w;
    }
    float bias = bd2[oc];
    float vals[4] = {s.x + bias, s.y + bias, s.z + bias, s.w + bias};
#pragma unroll
    for (int j = 0; j < 4; ++j) {
        int px = n0 + j;
        int b = px / 49, p = px - b * 49;
        float r = fmaxf(vals[j], 0.f);
        g_d2[b][oc][p] = r;
        __nv_bfloat16 hi, lo; split_bf16(r, hi, lo);
        g_d2h[(b * 49 + p) * 128 + oc] = hi;
        g_d2l[(b * 49 + p) * 128 + oc] = lo;
    }
}

__global__ void reduce3(const float* __restrict__ bd3) {
    int i = blockIdx.x * 256 + threadIdx.x;
    if (i >= 128 * 32) return;
    int oc = i / 32;
    int n0 = (i - oc * 32) * 4;
    float4 s = make_float4(0.f, 0.f, 0.f, 0.f);
#pragma unroll
    for (int j = 0; j < 36; ++j) {
        float4 v = *(const float4*)&g_p3w[j][oc][n0];
        s.x += v.x; s.y += v.y; s.z += v.z; s.w += v.w;
    }
    float bias = bd3[oc];
    float vals[4] = {s.x + bias, s.y + bias, s.z + bias, s.w + bias};
#pragma unroll
    for (int j = 0; j < 4; ++j) {
        int px = n0 + j;
        int b = px >> 4, p = px & 15;
        g_d3[b][oc][p] = fmaxf(vals[j], 0.f);
    }
}

// ---------------- heads ----------------
__global__ void heads_kernel(const float* __restrict__ wt1, const float* __restrict__ bt1,
                             const float* __restrict__ wt2, const float* __restrict__ bt2,
                             const float* __restrict__ wt3, const float* __restrict__ bt3) {
    int b = blockIdx.x;
    int a = blockIdx.y * 256 + threadIdx.x;
    if (a >= NA) return;
    float acc;
    if (a < 1176) {
        int c = a / 196, p = a - c * 196;
        acc = bt1[c];
        const float* w = wt1 + c * 128;
        for (int ic = 0; ic < 128; ++ic) acc += g_d1[b][ic][p] * w[ic];
    } else if (a < 1470) {
        int a2 = a - 1176;
        int c = a2 / 49, p = a2 - c * 49;
        acc = bt2[c];
        const float* w = wt2 + c * 128;
        for (int ic = 0; ic < 128; ++ic) acc += g_d2[b][ic][p] * w[ic];
    } else {
        int a3 = a - 1470;
        int c = a3 / 16, p = a3 & 15;
        acc = bt3[c];
        const float* w = wt3 + c * 128;
        for (int ic = 0; ic < 128; ++ic) acc += g_d3[b][ic][p] * w[ic];
    }
    g_scores[b][a] = acc;
}

// ---------------- NMS + top-6: hybrid reg/warp-shuffle bitonic sort ----------------
// Same compare-exchange network as before; kk<=64 phases and j<=32 passes run
// in registers (warp owns contiguous 64 elems, 2/lane), only j>=64 via shared.
__global__ __launch_bounds__(1024) void nms_topk_kernel(const float* __restrict__ anchors,
                                                        float* __restrict__ out) {
    __shared__ unsigned long long key[2048];
    const int b = blockIdx.x;
    const int t = threadIdx.x;
    const int l = t & 31, w = t >> 5;
    const int base = w * 64 + l * 2;

    auto mkkey = [&](int a) -> unsigned long long {
        if (a >= NA) return 0ull;
        unsigned u = __float_as_uint(g_scores[b][a]);
        unsigned us = (u & 0x80000000u) ? ~u : (u | 0x80000000u);
        return ((unsigned long long)us << 32) | (unsigned)(~(unsigned)a);
    };
    unsigned long long e0 = mkkey(base), e1 = mkkey(base + 1);

    auto inwarp = [&](int kk, int j) {
        bool desc = ((base & kk) == 0);
        if (j == 1) {
            bool sw = desc ? (e0 < e1) : (e0 > e1);
            if (sw) { unsigned long long tmp = e0; e0 = e1; e1 = tmp; }
        } else {
            unsigned long long o0 = __shfl_xor_sync(0xFFFFFFFFu, e0, j >> 1);
            unsigned long long o1 = __shfl_xor_sync(0xFFFFFFFFu, e1, j >> 1);
            bool low = ((base & j) == 0);
            bool keepmax = (desc == low);
            e0 = keepmax ? (e0 > o0 ? e0 : o0) : (e0 < o0 ? e0 : o0);
            e1 = keepmax ? (e1 > o1 ? e1 : o1) : (e1 < o1 ? e1 : o1);
        }
    };

    for (int kk = 2; kk <= 64; kk <<= 1)
        for (int j = kk >> 1; j >= 1; j >>= 1)
            inwarp(kk, j);

    for (int kk = 128; kk <= 2048; kk <<= 1) {
        key[base] = e0; key[base + 1] = e1;
        __syncthreads();
        for (int j = kk >> 1; j >= 64; j >>= 1) {
            for (int i = t; i < 2048; i += 1024) {
                int ixj = i ^ j;
                if (ixj > i) {
                    unsigned long long x = key[i], y = key[ixj];
                    bool desc = ((i & kk) == 0);
                    if (desc ? (x < y) : (x > y)) { key[i] = y; key[ixj] = x; }
                }
            }
            __syncthreads();
        }
        e0 = key[base]; e1 = key[base + 1];
        for (int j = 32; j >= 1; j >>= 1) inwarp(kk, j);
    }
    key[base] = e0; key[base + 1] = e1;
    __syncthreads();

    if (t == 0) {
        float ky0[TOPN], kx0[TOPN], ky1[TOPN], kx1[TOPN], karea[TOPN], kprob[TOPN];
        int kidx[TOPN];
        int nk = 0;
        for (int r = 0; r < NA && nk < TOPN; ++r) {
            unsigned long long k = key[r];
            int idx = (int)(~(unsigned)k);
            if (idx >= NA) break;
            float y0 = anchors[idx * 4 + 0], x0 = anchors[idx * 4 + 1];
            float y1 = anchors[idx * 4 + 2], x1 = anchors[idx * 4 + 3];
            float area = (y1 - y0) * (x1 - x0);
            bool sup = false;
            for (int s = 0; s < nk; ++s) {
                float ih = fminf(y1, ky1[s]) - fmaxf(y0, ky0[s]); if (ih < 0.f) ih = 0.f;
                float iw = fminf(x1, kx1[s]) - fmaxf(x0, kx0[s]); if (iw < 0.f) iw = 0.f;
                float inter = ih * iw;
                if (inter > 0.25f * (area + karea[s] - inter)) { sup = true; break; }
            }
            if (!sup) {
                unsigned us = (unsigned)(k >> 32);
                unsigned u = (us & 0x80000000u) ? (us ^ 0x80000000u) : ~us;
                ky0[nk] = y0; kx0[nk] = x0; ky1[nk] = y1; kx1[nk] = x1;
                karea[nk] = area; kidx[nk] = idx; kprob[nk] = __uint_as_float(u);
                ++nk;
            }
        }
        int fi = 0;
        while (nk < TOPN) {
            bool used = false;
            for (int s = 0; s < nk; ++s) if (kidx[s] == fi) used = true;
            if (!used) {
                ky0[nk] = anchors[fi * 4 + 0]; kx0[nk] = anchors[fi * 4 + 1];
                ky1[nk] = anchors[fi * 4 + 2]; kx1[nk] = anchors[fi * 4 + 3];
                karea[nk] = 0.f; kidx[nk] = fi; kprob[nk] = -INFINITY;
                ++nk;
            }
            ++fi;
        }
        for (int s = 0; s < TOPN; ++s) {
            int o = b * TOPN + s;
            g_boxes[b][s][0] = (int)kx0[s];
            g_boxes[b][s][1] = (int)ky0[s];
            g_boxes[b][s][2] = (int)kx1[s];
            g_boxes[b][s][3] = (int)ky1[s];
            out[OFF_COORDS + o * 4 + 0] = kx0[s];
            out[OFF_COORDS + o * 4 + 1] = ky0[s];
            out[OFF_COORDS + o * 4 + 2] = kx1[s];
            out[OFF_COORDS + o * 4 + 3] = ky1[s];
            out[OFF_PROB + o] = kprob[s];
            out[OFF_IDX + o] = (float)kidx[s];
        }
    }
}

// ---------------- crop-resize ----------------
__global__ __launch_bounds__(224) void crop_kernel(const float* __restrict__ xin,
                                                   float* __restrict__ out) {
    const int t  = threadIdx.x;
    const int xq = (t % 56) * 4;
    const int oy = blockIdx.x * 4 + t / 56;
    const int c  = blockIdx.y;
    const int bs = blockIdx.z;
    const int b  = bs / TOPN;
    const int s  = bs - b * TOPN;

    const int X0 = g_boxes[b][s][0], Y0 = g_boxes[b][s][1];
    const int X1 = g_boxes[b][s][2], Y1 = g_boxes[b][s][3];

    float ty = __fdiv_rn((float)oy, 223.0f);
    float sy = __fadd_rn((float)Y0, __fmul_rn(ty, (float)(Y1 - 1 - Y0)));
    int y0i = (int)floorf(sy);
    int y1i = min(y0i + 1, Y1 - 1);
    float wy = __fadd_rn(sy, -(float)y0i);

    const float* img = xin + ((size_t)b * 3 + c) * 448 * 448;
    auto fetch = [&](int y, int x) -> float {
        y -= 224; x -= 224;
        if ((unsigned)y < 448u && (unsigned)x < 448u) return img[y * 448 + x];
        return 0.f;
    };

    float4 res;
    float* rp = &res.x;
#pragma unroll
    for (int j = 0; j < 4; ++j) {
        int ox = xq + j;
        float tx = __fdiv_rn((float)ox, 223.0f);
        float sx = __fadd_rn((float)X0, __fmul_rn(tx, (float)(X1 - 1 - X0)));
        int x0i = (int)floorf(sx);
        int x1i = min(x0i + 1, X1 - 1);
        float wx = __fadd_rn(sx, -(float)x0i);

        float f00 = fetch(y0i, x0i), f01 = fetch(y0i, x1i);
        float f10 = fetch(y1i, x0i), f11 = fetch(y1i, x1i);
        float top = (1.f - wx) * f00 + wx * f01;
        float bot = (1.f - wx) * f10 + wx * f11;
        rp[j] = (1.f - wy) * top + wy * bot;
    }
    *(float4*)&out[(((size_t)bs * 3 + c) * OUTP + oy) * OUTP + xq] = res;
}

// ---------------- launch ----------------
extern "C" void kernel_launch(void* const* d_in, const int* in_sizes, int n_in,
                              void* d_out, int out_size) {
    const float* x       = (const float*)d_in[0];
    const float* rpn     = (const float*)d_in[1];
    const float* anchors = (const float*)d_in[2];
    const float* wd1 = (const float*)d_in[3];
    const float* bd1 = (const float*)d_in[4];
    const float* wd2 = (const float*)d_in[5];
    const float* bd2 = (const float*)d_in[6];
    const float* wd3 = (const float*)d_in[7];
    const float* bd3 = (const float*)d_in[8];
    const float* wt1 = (const float*)d_in[9];
    const float* bt1 = (const float*)d_in[10];
    const float* wt2 = (const float*)d_in[11];
    const float* bt2 = (const float*)d_in[12];
    const float* wt3 = (const float*)d_in[13];
    const float* bt3 = (const float*)d_in[14];
    float* out = (float*)d_out;

    cudaFuncSetAttribute(conv_wmma<1>, cudaFuncAttributeMaxDynamicSharedMemorySize, DYNSMEM);
    cudaFuncSetAttribute(conv_wmma<2>, cudaFuncAttributeMaxDynamicSharedMemorySize, DYNSMEM);
    cudaFuncSetAttribute(conv_wmma<3>, cudaFuncAttributeMaxDynamicSharedMemorySize, DYNSMEM);

    prep_all<<<1792, 256>>>(wd1, rpn, wd2, wd3);
    conv_wmma<1><<<NSLOT, 256, DYNSMEM>>>();
    reduce1<<<(128 * 392 + 255) / 256, 256>>>(bd1);
    conv_wmma<2><<<NS2, 256, DYNSMEM>>>();
    reduce2<<<(128 * 98 + 255) / 256, 256>>>(bd2);
    conv_wmma<3><<<NS3, 256, DYNSMEM>>>();
    reduce3<<<(128 * 32 + 255) / 256, 256>>>(bd3);
    heads_kernel<<<dim3(BATCH, 7), 256>>>(wt1, bt1, wt2, bt2, wt3, bt3);
    nms_topk_kernel<<<BATCH, 1024>>>(anchors, out);
    crop_kernel<<<dim3(56, 3, BATCH * TOPN), 224>>>(x, out);
}